// round 13
// baseline (speedup 1.0000x reference)
#include <cuda_runtime.h>
#include <cuda_bf16.h>
#include <cstdint>

#define NU 100000          // users
#define NM 20000           // movies
#define NE 1000000         // edges per direction
#define NLOOP 20000        // self loops (min(NU,NM))
#define ET (NE + NLOOP)
#define HD 64
#define WTOT (2 * 2 * 64 * 64)   // L * etype * H * H = 16384 per (Wl|Wr)

// ---------------- scratch (static device globals; zero at module load) ------
__device__ float g_sm[NM],   g_su[NU];        // segment sums of exp
__device__ float g_accm[(size_t)NM * HD];     // re-zeroed by finalize each layer
__device__ float g_accu[(size_t)NU * HD];
__device__ float g_xlu[(size_t)NU * HD];   // user  src-proj (xl of u2m)
__device__ float g_xru[(size_t)NU * HD];   // user  dst-proj (xr of m2u)
__device__ float g_xlm[(size_t)NM * HD];   // movie src-proj (xl of m2u)
__device__ float g_xrm[(size_t)NM * HD];   // movie dst-proj (xr of u2m)
__device__ float g_xu[(size_t)NU * HD];    // layer-0 user output
__device__ float g_xm[(size_t)NM * HD];    // layer-0 movie output
__device__ uint2 g_wl_sp[WTOT];            // pre-split (hi,lo) of Wl
__device__ uint2 g_wr_sp[WTOT];            // pre-split (hi,lo) of Wr

// ---------------- tf32 helpers ----------------------------------------------
__device__ __forceinline__ void split_tf32(float x, uint32_t& hi, uint32_t& lo)
{
    uint32_t h;
    asm("cvt.rna.tf32.f32 %0, %1;" : "=r"(h) : "f"(x));
    float r = x - __uint_as_float(h);
    uint32_t l;
    asm("cvt.rna.tf32.f32 %0, %1;" : "=r"(l) : "f"(r));
    hi = h; lo = l;
}

__device__ __forceinline__ void mma_tf32(float c[4],
                                         uint32_t a0, uint32_t a1, uint32_t a2, uint32_t a3,
                                         uint32_t b0, uint32_t b1)
{
    asm volatile("mma.sync.aligned.m16n8k8.row.col.f32.tf32.tf32.f32 "
                 "{%0,%1,%2,%3}, {%4,%5,%6,%7}, {%8,%9}, {%0,%1,%2,%3};"
                 : "+f"(c[0]), "+f"(c[1]), "+f"(c[2]), "+f"(c[3])
                 : "r"(a0), "r"(a1), "r"(a2), "r"(a3), "r"(b0), "r"(b1));
}

// ---------------- once-per-launch W split ------------------------------------
__global__ void wsplit_k(const float* __restrict__ Wl, const float* __restrict__ Wr,
                         uint2* __restrict__ wl_sp, uint2* __restrict__ wr_sp)
{
    int i = blockIdx.x * blockDim.x + threadIdx.x;
    if (i >= WTOT) return;
    uint32_t h, l;
    split_tf32(Wl[i], h, l);
    wl_sp[i] = make_uint2(h, l);
    split_tf32(Wr[i], h, l);
    wr_sp[i] = make_uint2(h, l);
}

// ---------------- tensor-core dual-side, dual-output GEMM --------------------
// blocks [0,GU): user rows; [GU,GU+GM): movie rows. Per block: 64 rows x both
// projections via 3xTF32 mma (fp32 accuracy). B operands come pre-split from
// global (hi,lo) planes (L1-resident). Also zeroes the segment-sum buffers.
__global__ void gemm2_tc_k(const float* __restrict__ Xu, const float* __restrict__ Xm,
                           const uint2* __restrict__ W1u, const float* __restrict__ B1u,
                           const uint2* __restrict__ W2u, const float* __restrict__ B2u,
                           const uint2* __restrict__ W1m, const float* __restrict__ B1m,
                           const uint2* __restrict__ W2m, const float* __restrict__ B2m,
                           float* __restrict__ Y1u, float* __restrict__ Y2u,
                           float* __restrict__ Y1m, float* __restrict__ Y2m,
                           float* __restrict__ sm_, float* __restrict__ su_,
                           int GU)
{
    // fused zeroing of segment-sum buffers (prior finalize already read them)
    for (int z = blockIdx.x * blockDim.x + threadIdx.x; z < NM + NU;
         z += gridDim.x * blockDim.x) {
        if (z < NM) sm_[z] = 0.f; else su_[z - NM] = 0.f;
    }

    __shared__ float Xs[64][68];     // stride 68: A-frag LDS is bank-conflict-free

    int tid = threadIdx.x;           // 256 threads
    int bid = blockIdx.x;

    const float *X, *B1, *B2;
    const uint2 *W1, *W2;
    float *Y1, *Y2;
    int N;
    if (bid < GU) {
        X = Xu; W1 = W1u; B1 = B1u; W2 = W2u; B2 = B2u;
        Y1 = Y1u; Y2 = Y2u; N = NU;
    } else {
        bid -= GU;
        X = Xm; W1 = W1m; B1 = B1m; W2 = W2m; B2 = B2m;
        Y1 = Y1m; Y2 = Y2m; N = NM;
    }
    int rowblk = bid * 64;

    // fill Xs[64][64 used of 68]
#pragma unroll
    for (int i = 0; i < 4; i++) {
        int idx = tid + i * 256;     // float4 index over [64][16]
        int r = idx >> 4, c4 = idx & 15;
        float4 v = make_float4(0.f, 0.f, 0.f, 0.f);
        if (rowblk + r < N) v = ((const float4*)X)[(size_t)(rowblk + r) * 16 + c4];
        *(float4*)&Xs[r][c4 * 4] = v;
    }
    __syncthreads();

    int wid  = tid >> 5;
    int lane = tid & 31;
    int warp_m = wid & 3;            // row group of 16
    int warp_n = wid >> 2;           // 0 -> (W1,B1,Y1), 1 -> (W2,B2,Y2)
    const uint2* W  = warp_n ? W2 : W1;
    const float* Bv = warp_n ? B2 : B1;
    float*       Y  = warp_n ? Y2 : Y1;

    int row0 = warp_m * 16;
    int qid = lane >> 2;             // t/4 : 0..7
    int rid = lane & 3;              // t%4 : 0..3

    float c[8][4];
#pragma unroll
    for (int nt = 0; nt < 8; nt++)
#pragma unroll
        for (int j = 0; j < 4; j++) c[nt][j] = 0.f;

#pragma unroll
    for (int k0 = 0; k0 < 64; k0 += 8) {
        // A fragment (m16 x k8), rows row0+qid / +8, cols k0+rid / +4
        float fa0 = Xs[row0 + qid    ][k0 + rid    ];
        float fa1 = Xs[row0 + qid + 8][k0 + rid    ];
        float fa2 = Xs[row0 + qid    ][k0 + rid + 4];
        float fa3 = Xs[row0 + qid + 8][k0 + rid + 4];
        uint32_t ah0, al0, ah1, al1, ah2, al2, ah3, al3;
        split_tf32(fa0, ah0, al0);
        split_tf32(fa1, ah1, al1);
        split_tf32(fa2, ah2, al2);
        split_tf32(fa3, ah3, al3);

        const uint2* wrow0 = W + (k0 + rid) * 64;
        const uint2* wrow1 = wrow0 + 4 * 64;
#pragma unroll
        for (int nt = 0; nt < 8; nt++) {
            int n = nt * 8 + qid;    // B col
            uint2 b0 = __ldg(&wrow0[n]);   // (hi,lo) of W[k0+rid][n]
            uint2 b1 = __ldg(&wrow1[n]);   // (hi,lo) of W[k0+rid+4][n]
            mma_tf32(c[nt], ah0, ah1, ah2, ah3, b0.x, b1.x);   // hi*hi
            mma_tf32(c[nt], ah0, ah1, ah2, ah3, b0.y, b1.y);   // hi*lo
            mma_tf32(c[nt], al0, al1, al2, al3, b0.x, b1.x);   // lo*hi
        }
    }

    // epilogue: + bias, store float2 pairs
    int r0 = rowblk + row0 + qid;
    int r1 = r0 + 8;
#pragma unroll
    for (int nt = 0; nt < 8; nt++) {
        int cb = nt * 8 + rid * 2;
        float2 bv = *(const float2*)&Bv[cb];
        if (r0 < N) {
            float2 o; o.x = c[nt][0] + bv.x; o.y = c[nt][1] + bv.y;
            *(float2*)&Y[(size_t)r0 * 64 + cb] = o;
        }
        if (r1 < N) {
            float2 o; o.x = c[nt][2] + bv.x; o.y = c[nt][3] + bv.y;
            *(float2*)&Y[(size_t)r1 * 64 + cb] = o;
        }
    }
}

// ---------------- fused edge pass, both directions in one launch -------------
__global__ void conv_dual_k(const int* __restrict__ eu, const int* __restrict__ em,
                            const float* __restrict__ xlu, const float* __restrict__ xrm,
                            const float* __restrict__ xlm, const float* __restrict__ xru,
                            const float* __restrict__ att0, const float* __restrict__ att1,
                            float* __restrict__ sm_, float* __restrict__ su_,
                            float* __restrict__ accm, float* __restrict__ accu,
                            int CB)
{
    const int *esrc, *edst;
    const float *xl, *xr, *att;
    float *sbuf, *acc;
    int bid = blockIdx.x;
    if (bid < CB) {
        esrc = eu; edst = eu + NE; xl = xlu; xr = xrm; att = att0;
        sbuf = sm_; acc = accm;
    } else {
        bid -= CB;
        esrc = em; edst = em + NE; xl = xlm; xr = xru; att = att1;
        sbuf = su_; acc = accu;
    }

    int t = bid * blockDim.x + threadIdx.x;
    int g = t >> 4;
    if (g >= ET) return;
    int lane = t & 15;
    int s, d;
    if (g < NE) { s = esrc[g]; d = edst[g]; } else { s = g - NE; d = s; }

    float4 a = ((const float4*)xl)[(size_t)s * 16 + lane];
    float4 b = ((const float4*)xr)[(size_t)d * 16 + lane];
    float4 w = ((const float4*)att)[lane];

    float vx = a.x + b.x; vx = vx > 0.f ? vx : 0.2f * vx;
    float vy = a.y + b.y; vy = vy > 0.f ? vy : 0.2f * vy;
    float vz = a.z + b.z; vz = vz > 0.f ? vz : 0.2f * vz;
    float vw = a.w + b.w; vw = vw > 0.f ? vw : 0.2f * vw;
    float p = vx * w.x + vy * w.y + vz * w.z + vw * w.w;
#pragma unroll
    for (int o = 8; o > 0; o >>= 1) p += __shfl_xor_sync(0xffffffffu, p, o);
    float ex = __expf(p);

    if (lane == 0) atomicAdd(&sbuf[d], ex);

    a.x *= ex; a.y *= ex; a.z *= ex; a.w *= ex;
    float* pp = acc + (size_t)d * HD + lane * 4;
    asm volatile("red.global.add.v4.f32 [%0], {%1,%2,%3,%4};"
                 :: "l"(pp), "f"(a.x), "f"(a.y), "f"(a.z), "f"(a.w) : "memory");
}

// ---------------- finalize (float4) + re-zero acc ----------------------------
__global__ void finalize2_k(float* __restrict__ accm, const float* __restrict__ sm_,
                            const float* __restrict__ bias0, float* __restrict__ outm,
                            float* __restrict__ accu, const float* __restrict__ su_,
                            const float* __restrict__ bias1, float* __restrict__ outu)
{
    int i = blockIdx.x * blockDim.x + threadIdx.x;   // float4 index
    const int NM4 = NM * (HD / 4);
    const int NT4 = (NM + NU) * (HD / 4);
    if (i >= NT4) return;

    float* acc; const float* sbuf; const float* bias; float* out; int j;
    if (i < NM4) { acc = accm; sbuf = sm_; bias = bias0; out = outm; j = i; }
    else         { acc = accu; sbuf = su_; bias = bias1; out = outu; j = i - NM4; }

    int row = j >> 4;
    int c4  = j & 15;
    float inv = 1.f / (sbuf[row] + 1e-16f);
    float4 a = ((const float4*)acc)[j];
    float4 b = ((const float4*)bias)[c4];

    const float SCALE = 1.0507009873554805f;
    const float SA    = 1.7580993408473766f;   // scale * alpha
    float4 o;
    o.x = a.x * inv + b.x; o.x = o.x > 0.f ? SCALE * o.x : SA * (__expf(o.x) - 1.f);
    o.y = a.y * inv + b.y; o.y = o.y > 0.f ? SCALE * o.y : SA * (__expf(o.y) - 1.f);
    o.z = a.z * inv + b.z; o.z = o.z > 0.f ? SCALE * o.z : SA * (__expf(o.z) - 1.f);
    o.w = a.w * inv + b.w; o.w = o.w > 0.f ? SCALE * o.w : SA * (__expf(o.w) - 1.f);

    ((float4*)out)[j] = o;
    ((float4*)acc)[j] = make_float4(0.f, 0.f, 0.f, 0.f);   // re-zero for next use
}

// ---------------- host ------------------------------------------------------
extern "C" void kernel_launch(void* const* d_in, const int* in_sizes, int n_in,
                              void* d_out, int out_size)
{
    const float* x_user  = (const float*)d_in[0];
    const float* x_movie = (const float*)d_in[1];
    const int*   e_u2m   = (const int*)d_in[2];
    const int*   e_m2u   = (const int*)d_in[3];
    const float* Wl      = (const float*)d_in[4];
    const float* bl      = (const float*)d_in[5];
    const float* Wr      = (const float*)d_in[6];
    const float* br      = (const float*)d_in[7];
    const float* att     = (const float*)d_in[8];
    const float* bias    = (const float*)d_in[9];
    float* out = (float*)d_out;

    float *sm, *su, *accm, *accu, *xlu, *xru, *xlm, *xrm, *xu, *xm;
    uint2 *wl_sp, *wr_sp;
    cudaGetSymbolAddress((void**)&sm,    g_sm);
    cudaGetSymbolAddress((void**)&su,    g_su);
    cudaGetSymbolAddress((void**)&accm,  g_accm);
    cudaGetSymbolAddress((void**)&accu,  g_accu);
    cudaGetSymbolAddress((void**)&xlu,   g_xlu);
    cudaGetSymbolAddress((void**)&xru,   g_xru);
    cudaGetSymbolAddress((void**)&xlm,   g_xlm);
    cudaGetSymbolAddress((void**)&xrm,   g_xrm);
    cudaGetSymbolAddress((void**)&xu,    g_xu);
    cudaGetSymbolAddress((void**)&xm,    g_xm);
    cudaGetSymbolAddress((void**)&wl_sp, g_wl_sp);
    cudaGetSymbolAddress((void**)&wr_sp, g_wr_sp);

    const int GU  = (NU + 63) / 64;               // 1563 user gemm blocks
    const int GM  = (NM + 63) / 64;               // 313 movie gemm blocks
    const int CB  = ((long)ET * 16 + 255) / 256;  // 63750 conv blocks per direction
    const int FB4 = ((NM + NU) * (HD / 4) + 255) / 256;

    // once-per-launch pre-split of all weight matrices
    wsplit_k<<<(WTOT + 255) / 256, 256>>>(Wl, Wr, wl_sp, wr_sp);

    const float* cu = x_user;
    const float* cm = x_movie;

    for (int l = 0; l < 2; l++) {
        int p0 = l * 2 + 0;   // user -> movie
        int p1 = l * 2 + 1;   // movie -> user

        gemm2_tc_k<<<GU + GM, 256>>>(cu, cm,
            wl_sp + (size_t)p0 * 4096, bl + (size_t)p0 * 64,
            wr_sp + (size_t)p1 * 4096, br + (size_t)p1 * 64,
            wl_sp + (size_t)p1 * 4096, bl + (size_t)p1 * 64,
            wr_sp + (size_t)p0 * 4096, br + (size_t)p0 * 64,
            xlu, xru, xlm, xrm, sm, su, GU);

        conv_dual_k<<<2 * CB, 256>>>(e_u2m, e_m2u, xlu, xrm, xlm, xru,
            att + (size_t)p0 * 64, att + (size_t)p1 * 64,
            sm, su, accm, accu, CB);

        float* om = (l == 1) ? (out + (size_t)NU * HD) : xm;
        float* ou = (l == 1) ? out : xu;
        finalize2_k<<<FB4, 256>>>(accm, sm, bias + (size_t)p0 * 64, om,
                                  accu, su, bias + (size_t)p1 * 64, ou);

        cu = xu;
        cm = xm;
    }
}

// round 15
// speedup vs baseline: 1.1463x; 1.1463x over previous
#include <cuda_runtime.h>
#include <cuda_bf16.h>
#include <cstdint>

#define NU 100000          // users
#define NM 20000           // movies
#define NE 1000000         // edges per direction
#define NLOOP 20000        // self loops (min(NU,NM))
#define ET (NE + NLOOP)
#define HD 64

// ---------------- scratch (static device globals; zero at module load) ------
__device__ float g_smA[NM],  g_suA[NU];       // layer-0 segment sums
__device__ float g_smB[NM],  g_suB[NU];       // layer-1 segment sums
__device__ float g_accm[(size_t)NM * HD];     // re-zeroed by each consumer
__device__ float g_accu[(size_t)NU * HD];
__device__ float g_xlu[(size_t)NU * HD];   // user  src-proj (xl of u2m)
__device__ float g_xru[(size_t)NU * HD];   // user  dst-proj (xr of m2u)
__device__ float g_xlm[(size_t)NM * HD];   // movie src-proj (xl of m2u)
__device__ float g_xrm[(size_t)NM * HD];   // movie dst-proj (xr of u2m)

// ---------------- helpers ----------------------------------------------------
__device__ __forceinline__ float selu_f(float x)
{
    const float SCALE = 1.0507009873554805f;
    const float SA    = 1.7580993408473766f;   // scale * alpha
    return x > 0.f ? SCALE * x : SA * (__expf(x) - 1.f);
}

__device__ __forceinline__ void split_tf32(float x, uint32_t& hi, uint32_t& lo)
{
    uint32_t h;
    asm("cvt.rna.tf32.f32 %0, %1;" : "=r"(h) : "f"(x));
    float r = x - __uint_as_float(h);
    uint32_t l;
    asm("cvt.rna.tf32.f32 %0, %1;" : "=r"(l) : "f"(r));
    hi = h; lo = l;
}

__device__ __forceinline__ void mma_tf32(float c[4],
                                         uint32_t a0, uint32_t a1, uint32_t a2, uint32_t a3,
                                         uint32_t b0, uint32_t b1)
{
    asm volatile("mma.sync.aligned.m16n8k8.row.col.f32.tf32.tf32.f32 "
                 "{%0,%1,%2,%3}, {%4,%5,%6,%7}, {%8,%9}, {%0,%1,%2,%3};"
                 : "+f"(c[0]), "+f"(c[1]), "+f"(c[2]), "+f"(c[3])
                 : "r"(a0), "r"(a1), "r"(a2), "r"(a3), "r"(b0), "r"(b1));
}

// ---------------- tensor-core dual-side, dual-output GEMM --------------------
// blocks [0,GU): user rows; [GU,GU+GM): movie rows. Per block: 64 rows x both
// projections via 3xTF32 mma (fp32 accuracy, R10-proven body).
// fused=0: X comes from Xu/Xm directly.
// fused=1: X = selu(acc/segsum + bias_prev), read from accU/accM (re-zeroed in
//          place after read), using the PREVIOUS layer's segment sums.
// Always zeroes THIS layer's segment-sum pair (smZ/suZ) via grid-stride.
__global__ void gemm2_tc_k(const float* __restrict__ Xu, const float* __restrict__ Xm,
                           const float* __restrict__ W1u, const float* __restrict__ B1u,
                           const float* __restrict__ W2u, const float* __restrict__ B2u,
                           const float* __restrict__ W1m, const float* __restrict__ B1m,
                           const float* __restrict__ W2m, const float* __restrict__ B2m,
                           float* __restrict__ Y1u, float* __restrict__ Y2u,
                           float* __restrict__ Y1m, float* __restrict__ Y2m,
                           float* __restrict__ smZ, float* __restrict__ suZ,
                           int fused,
                           float* __restrict__ accU, float* __restrict__ accM,
                           const float* __restrict__ suIn, const float* __restrict__ smIn,
                           const float* __restrict__ biasU, const float* __restrict__ biasM,
                           int GU)
{
    // zero THIS layer's segment-sum buffers (their last consumer already ran)
    for (int z = blockIdx.x * blockDim.x + threadIdx.x; z < NM + NU;
         z += gridDim.x * blockDim.x) {
        if (z < NM) smZ[z] = 0.f; else suZ[z - NM] = 0.f;
    }

    __shared__ float Xs[64][68];     // stride 68: A-frag LDS is bank-conflict-free

    int tid = threadIdx.x;           // 256 threads
    int bid = blockIdx.x;

    const float *X, *B1, *B2;
    const float *W1, *W2;
    float *Y1, *Y2;
    float *accX; const float *sIn, *biasP;
    int N;
    if (bid < GU) {
        X = Xu; W1 = W1u; B1 = B1u; W2 = W2u; B2 = B2u;
        Y1 = Y1u; Y2 = Y2u; N = NU;
        accX = accU; sIn = suIn; biasP = biasU;
    } else {
        bid -= GU;
        X = Xm; W1 = W1m; B1 = B1m; W2 = W2m; B2 = B2m;
        Y1 = Y1m; Y2 = Y2m; N = NM;
        accX = accM; sIn = smIn; biasP = biasM;
    }
    int rowblk = bid * 64;

    // fill Xs[64][64 used of 68]
#pragma unroll
    for (int i = 0; i < 4; i++) {
        int idx = tid + i * 256;     // float4 index over [64][16]
        int r = idx >> 4, c4 = idx & 15;
        int grow = rowblk + r;
        float4 v = make_float4(0.f, 0.f, 0.f, 0.f);
        if (grow < N) {
            if (!fused) {
                v = ((const float4*)X)[(size_t)grow * 16 + c4];
            } else {
                float4 a = ((const float4*)accX)[(size_t)grow * 16 + c4];
                float inv = 1.f / (sIn[grow] + 1e-16f);
                float4 b = ((const float4*)biasP)[c4];
                v.x = selu_f(a.x * inv + b.x);
                v.y = selu_f(a.y * inv + b.y);
                v.z = selu_f(a.z * inv + b.z);
                v.w = selu_f(a.w * inv + b.w);
                // re-zero acc in place for this layer's conv (exactly-once per elem)
                ((float4*)accX)[(size_t)grow * 16 + c4] = make_float4(0.f, 0.f, 0.f, 0.f);
            }
        }
        *(float4*)&Xs[r][c4 * 4] = v;
    }
    __syncthreads();

    int wid  = tid >> 5;
    int lane = tid & 31;
    int warp_m = wid & 3;            // row group of 16
    int warp_n = wid >> 2;           // 0 -> (W1,B1,Y1), 1 -> (W2,B2,Y2)
    const float* W  = warp_n ? W2 : W1;
    const float* Bv = warp_n ? B2 : B1;
    float*       Y  = warp_n ? Y2 : Y1;

    int row0 = warp_m * 16;
    int qid = lane >> 2;             // t/4 : 0..7
    int rid = lane & 3;              // t%4 : 0..3

    float c[8][4];
#pragma unroll
    for (int nt = 0; nt < 8; nt++)
#pragma unroll
        for (int j = 0; j < 4; j++) c[nt][j] = 0.f;

#pragma unroll
    for (int k0 = 0; k0 < 64; k0 += 8) {
        // A fragment (m16 x k8), rows row0+qid / +8, cols k0+rid / +4
        float fa0 = Xs[row0 + qid    ][k0 + rid    ];
        float fa1 = Xs[row0 + qid + 8][k0 + rid    ];
        float fa2 = Xs[row0 + qid    ][k0 + rid + 4];
        float fa3 = Xs[row0 + qid + 8][k0 + rid + 4];
        uint32_t ah0, al0, ah1, al1, ah2, al2, ah3, al3;
        split_tf32(fa0, ah0, al0);
        split_tf32(fa1, ah1, al1);
        split_tf32(fa2, ah2, al2);
        split_tf32(fa3, ah3, al3);

#pragma unroll
        for (int nt = 0; nt < 8; nt++) {
            // B fragment (k8 x n8): b0 = W[k0+rid][n], b1 = W[k0+rid+4][n], n = nt*8+qid
            int n = nt * 8 + qid;
            float fb0 = __ldg(&W[(k0 + rid    ) * 64 + n]);
            float fb1 = __ldg(&W[(k0 + rid + 4) * 64 + n]);
            uint32_t bh0, bl0, bh1, bl1;
            split_tf32(fb0, bh0, bl0);
            split_tf32(fb1, bh1, bl1);

            mma_tf32(c[nt], ah0, ah1, ah2, ah3, bh0, bh1);   // hi*hi
            mma_tf32(c[nt], ah0, ah1, ah2, ah3, bl0, bl1);   // hi*lo
            mma_tf32(c[nt], al0, al1, al2, al3, bh0, bh1);   // lo*hi
        }
    }

    // epilogue: + bias, store float2 pairs
    int r0 = rowblk + row0 + qid;
    int r1 = r0 + 8;
#pragma unroll
    for (int nt = 0; nt < 8; nt++) {
        int cb = nt * 8 + rid * 2;
        float2 bv = *(const float2*)&Bv[cb];
        if (r0 < N) {
            float2 o; o.x = c[nt][0] + bv.x; o.y = c[nt][1] + bv.y;
            *(float2*)&Y[(size_t)r0 * 64 + cb] = o;
        }
        if (r1 < N) {
            float2 o; o.x = c[nt][2] + bv.x; o.y = c[nt][3] + bv.y;
            *(float2*)&Y[(size_t)r1 * 64 + cb] = o;
        }
    }
}

// ---------------- fused edge pass, both directions in one launch -------------
__global__ void conv_dual_k(const int* __restrict__ eu, const int* __restrict__ em,
                            const float* __restrict__ xlu, const float* __restrict__ xrm,
                            const float* __restrict__ xlm, const float* __restrict__ xru,
                            const float* __restrict__ att0, const float* __restrict__ att1,
                            float* __restrict__ sm_, float* __restrict__ su_,
                            float* __restrict__ accm, float* __restrict__ accu,
                            int CB)
{
    const int *esrc, *edst;
    const float *xl, *xr, *att;
    float *sbuf, *acc;
    int bid = blockIdx.x;
    if (bid < CB) {
        esrc = eu; edst = eu + NE; xl = xlu; xr = xrm; att = att0;
        sbuf = sm_; acc = accm;
    } else {
        bid -= CB;
        esrc = em; edst = em + NE; xl = xlm; xr = xru; att = att1;
        sbuf = su_; acc = accu;
    }

    int t = bid * blockDim.x + threadIdx.x;
    int g = t >> 4;
    if (g >= ET) return;
    int lane = t & 15;
    int s, d;
    if (g < NE) { s = esrc[g]; d = edst[g]; } else { s = g - NE; d = s; }

    float4 a = ((const float4*)xl)[(size_t)s * 16 + lane];
    float4 b = ((const float4*)xr)[(size_t)d * 16 + lane];
    float4 w = ((const float4*)att)[lane];

    float vx = a.x + b.x; vx = vx > 0.f ? vx : 0.2f * vx;
    float vy = a.y + b.y; vy = vy > 0.f ? vy : 0.2f * vy;
    float vz = a.z + b.z; vz = vz > 0.f ? vz : 0.2f * vz;
    float vw = a.w + b.w; vw = vw > 0.f ? vw : 0.2f * vw;
    float p = vx * w.x + vy * w.y + vz * w.z + vw * w.w;
#pragma unroll
    for (int o = 8; o > 0; o >>= 1) p += __shfl_xor_sync(0xffffffffu, p, o);
    float ex = __expf(p);

    if (lane == 0) atomicAdd(&sbuf[d], ex);

    a.x *= ex; a.y *= ex; a.z *= ex; a.w *= ex;
    float* pp = acc + (size_t)d * HD + lane * 4;
    asm volatile("red.global.add.v4.f32 [%0], {%1,%2,%3,%4};"
                 :: "l"(pp), "f"(a.x), "f"(a.y), "f"(a.z), "f"(a.w) : "memory");
}

// ---------------- finalize (float4) + re-zero acc (final layer only) ---------
__global__ void finalize2_k(float* __restrict__ accm, const float* __restrict__ sm_,
                            const float* __restrict__ bias0, float* __restrict__ outm,
                            float* __restrict__ accu, const float* __restrict__ su_,
                            const float* __restrict__ bias1, float* __restrict__ outu)
{
    int i = blockIdx.x * blockDim.x + threadIdx.x;   // float4 index
    const int NM4 = NM * (HD / 4);
    const int NT4 = (NM + NU) * (HD / 4);
    if (i >= NT4) return;

    float* acc; const float* sbuf; const float* bias; float* out; int j;
    if (i < NM4) { acc = accm; sbuf = sm_; bias = bias0; out = outm; j = i; }
    else         { acc = accu; sbuf = su_; bias = bias1; out = outu; j = i - NM4; }

    int row = j >> 4;
    int c4  = j & 15;
    float inv = 1.f / (sbuf[row] + 1e-16f);
    float4 a = ((const float4*)acc)[j];
    float4 b = ((const float4*)bias)[c4];

    float4 o;
    o.x = selu_f(a.x * inv + b.x);
    o.y = selu_f(a.y * inv + b.y);
    o.z = selu_f(a.z * inv + b.z);
    o.w = selu_f(a.w * inv + b.w);

    ((float4*)out)[j] = o;
    ((float4*)acc)[j] = make_float4(0.f, 0.f, 0.f, 0.f);   // re-zero for next replay
}

// ---------------- host ------------------------------------------------------
extern "C" void kernel_launch(void* const* d_in, const int* in_sizes, int n_in,
                              void* d_out, int out_size)
{
    const float* x_user  = (const float*)d_in[0];
    const float* x_movie = (const float*)d_in[1];
    const int*   e_u2m   = (const int*)d_in[2];
    const int*   e_m2u   = (const int*)d_in[3];
    const float* Wl      = (const float*)d_in[4];
    const float* bl      = (const float*)d_in[5];
    const float* Wr      = (const float*)d_in[6];
    const float* br      = (const float*)d_in[7];
    const float* att     = (const float*)d_in[8];
    const float* bias    = (const float*)d_in[9];
    float* out = (float*)d_out;

    float *smA, *suA, *smB, *suB, *accm, *accu, *xlu, *xru, *xlm, *xrm;
    cudaGetSymbolAddress((void**)&smA,  g_smA);
    cudaGetSymbolAddress((void**)&suA,  g_suA);
    cudaGetSymbolAddress((void**)&smB,  g_smB);
    cudaGetSymbolAddress((void**)&suB,  g_suB);
    cudaGetSymbolAddress((void**)&accm, g_accm);
    cudaGetSymbolAddress((void**)&accu, g_accu);
    cudaGetSymbolAddress((void**)&xlu,  g_xlu);
    cudaGetSymbolAddress((void**)&xru,  g_xru);
    cudaGetSymbolAddress((void**)&xlm,  g_xlm);
    cudaGetSymbolAddress((void**)&xrm,  g_xrm);

    const int GU  = (NU + 63) / 64;               // 1563 user gemm blocks
    const int GM  = (NM + 63) / 64;               // 313 movie gemm blocks
    const int CB  = ((long)ET * 16 + 255) / 256;  // 63750 conv blocks per direction
    const int FB4 = ((NM + NU) * (HD / 4) + 255) / 256;

    // ---- layer 0 -----------------------------------------------------------
    // p0 = 0 (u2m), p1 = 1 (m2u)
    gemm2_tc_k<<<GU + GM, 256>>>(x_user, x_movie,
        Wl + 0 * 4096, bl + 0 * 64,     // user xl (u2m, etype 0)
        Wr + 1 * 4096, br + 1 * 64,     // user xr (m2u, etype 1)
        Wl + 1 * 4096, bl + 1 * 64,     // movie xl (m2u)
        Wr + 0 * 4096, br + 0 * 64,     // movie xr (u2m)
        xlu, xru, xlm, xrm, smA, suA,
        /*fused=*/0, nullptr, nullptr, nullptr, nullptr, nullptr, nullptr, GU);

    conv_dual_k<<<2 * CB, 256>>>(e_u2m, e_m2u, xlu, xrm, xlm, xru,
        att + 0 * 64, att + 1 * 64, smA, suA, accm, accu, CB);

    // ---- layer 1 (finalize of layer 0 fused into this GEMM's X load) -------
    // layer-1 params: p0 = 2 (u2m), p1 = 3 (m2u)
    gemm2_tc_k<<<GU + GM, 256>>>(nullptr, nullptr,
        Wl + 2 * 4096, bl + 2 * 64,
        Wr + 3 * 4096, br + 3 * 64,
        Wl + 3 * 4096, bl + 3 * 64,
        Wr + 2 * 4096, br + 2 * 64,
        xlu, xru, xlm, xrm, smB, suB,
        /*fused=*/1, accu, accm, suA, smA,
        bias + 1 * 64 /*user bias l0*/, bias + 0 * 64 /*movie bias l0*/, GU);

    conv_dual_k<<<2 * CB, 256>>>(e_u2m, e_m2u, xlu, xrm, xlm, xru,
        att + 2 * 64, att + 3 * 64, smB, suB, accm, accu, CB);

    finalize2_k<<<FB4, 256>>>(accm, smB, bias + 2 * 64, out + (size_t)NU * HD,
                              accu, suB, bias + 3 * 64, out);
}